// round 2
// baseline (speedup 1.0000x reference)
#include <cuda_runtime.h>
#include <math.h>

// ---------------- problem constants ----------------
#define BATCH   262144
#define DMEM    100
#define NBLK    4096          // BATCH / 64
#define GCOLS   400           // [g_r(100), g_z(100), i_n(100), h_n(100)]
#define KTOT    404           // [mem[src](100), mem[dst](100), msg(4), t_enc(100), h(100)]
#define WB_COLS 448           // GCOLS padded to 7*64

// ---------------- scratch (static device globals; no allocation) ----------------
__device__ float g_scr[104857600];   // BATCH x 400
__device__ float a_scr[16777216];    // BATCH x 64
__device__ float Wbig[404 * 448];    // k-major packed weights, zero padded
__device__ float B400[400];          // fused biases
__device__ float p_sum[NBLK * 64];
__device__ float p_sq[NBLK * 64];
__device__ float W2e[128];
__device__ float b2e[2];

// accurate cos independent of -use_fast_math (args up to ~1e5)
__device__ __forceinline__ float cos_acc(float x) {
    double xd = (double)x;
    double k  = rint(xd * 0.15915494309189534);
    float  r  = (float)(xd - k * 6.283185307179586476925286766559);
    return cosf(r);
}

// ---------------- K0: pack weights + biases ----------------
__global__ void k0_prep(const float* __restrict__ W_ih, const float* __restrict__ W_hh,
                        const float* __restrict__ b_ih, const float* __restrict__ b_hh) {
    int idx0 = blockIdx.x * blockDim.x + threadIdx.x;
    int stride = gridDim.x * blockDim.x;
    for (int idx = idx0; idx < KTOT * WB_COLS; idx += stride) {
        int k = idx / WB_COLS;
        int c = idx - k * WB_COLS;
        float v = 0.f;
        if (c < GCOLS) {
            if (k < 304) {                   // x part
                if (c < 300) v = W_ih[c * 304 + k];
            } else {                          // h part
                int kh = k - 304;
                if (c < 200)       v = W_hh[c * 100 + kh];
                else if (c >= 300) v = W_hh[(c - 100) * 100 + kh];
            }
        }
        Wbig[idx] = v;
    }
    if (idx0 < 400) {
        int c = idx0;
        float bv;
        if (c < 200)      bv = b_ih[c] + b_hh[c];
        else if (c < 300) bv = b_ih[c];
        else              bv = b_hh[c - 100];
        B400[c] = bv;
    }
}

// ---------------- K1: gather + t_enc + big GEMM (G = U @ Wbig) ----------------
// block = 256 threads, 64 rows/block. Shared: U [64][404] row-major,
// Wsh [64k][64c], time params. 4x4 microtile per thread, 16x16 thread grid.
#define SMEM1_FLOATS (64 * 404 + 64 * 64 + 200)

__global__ void __launch_bounds__(256, 1)
k1_gemm(const int* __restrict__ n_id, const float* __restrict__ memory,
        const int* __restrict__ last_update, const int* __restrict__ store_src,
        const int* __restrict__ store_dst, const int* __restrict__ store_t,
        const float* __restrict__ store_msg, const float* __restrict__ time_w,
        const float* __restrict__ time_b) {
    extern __shared__ float sh[];
    float* Ush = sh;                    // [64][404]
    float* Wsh = sh + 64 * 404;         // [64][64]
    float* stw = Wsh + 64 * 64;         // [100]
    float* stb = stw + 100;             // [100]
    __shared__ int   s_src[64], s_dst[64], s_nid[64];
    __shared__ float s_dt[64];

    const int tid  = threadIdx.x;
    const int row0 = blockIdx.x << 6;

    if (tid < 64) {
        int nid = n_id[row0 + tid];
        s_nid[tid] = nid;
        s_src[tid] = store_src[nid];
        s_dst[tid] = store_dst[nid];
        s_dt[tid]  = (float)(store_t[nid] - last_update[nid]);
    }
    if (tid < 100) { stw[tid] = time_w[tid]; stb[tid] = time_b[tid]; }
    __syncthreads();

    // build U tile: gathers + msg + time encoding (coalesced per row, conflict-free STS)
    for (int i = tid; i < 6400; i += 256) {
        int r = i / 100;
        int c = i - r * 100;
        Ush[r * KTOT + c]        = memory[(size_t)s_src[r] * DMEM + c];
        Ush[r * KTOT + 100 + c]  = memory[(size_t)s_dst[r] * DMEM + c];
        Ush[r * KTOT + 304 + c]  = memory[(size_t)s_nid[r] * DMEM + c];
        float arg = __fadd_rn(__fmul_rn(s_dt[r], stw[c]), stb[c]);
        Ush[r * KTOT + 204 + c]  = cos_acc(arg);
    }
    { // msg (4 per row)
        int r = tid >> 2, m = tid & 3;
        Ush[r * KTOT + 200 + m] = store_msg[(size_t)s_nid[r] * 4 + m];
    }
    __syncthreads();

    const int tx = tid & 15;   // col group (4 cols)
    const int ty = tid >> 4;   // row group (4 rows)

    for (int cc = 0; cc < 7; cc++) {
        float acc[4][4];
        #pragma unroll
        for (int i = 0; i < 4; i++)
            #pragma unroll
            for (int j = 0; j < 4; j++) acc[i][j] = 0.f;

        const int k0 = (cc >= 5) ? 304 : 0;   // cols >=320 only need the h part
        for (int kk = k0; kk < KTOT; kk += 64) {
            // cooperative load of W block (vectorized, zero-padded k tail)
            #pragma unroll 4
            for (int i = tid; i < 1024; i += 256) {
                int k  = i >> 4;
                int c4 = (i & 15) << 2;
                int kg = kk + k;
                float4 v = make_float4(0.f, 0.f, 0.f, 0.f);
                if (kg < KTOT) v = *(const float4*)&Wbig[kg * WB_COLS + (cc << 6) + c4];
                ((float4*)Wsh)[i] = v;
            }
            __syncthreads();

            const float* Up = &Ush[(ty << 2) * KTOT + kk];
            const float* Wp = &Wsh[tx << 2];
            #pragma unroll 8
            for (int k = 0; k < 64; k++) {
                // note: U reads past k=403 hit zero weights -> harmless finite*0
                float4 w = *(const float4*)(Wp + (k << 6));
                float u0 = Up[k];
                float u1 = Up[KTOT + k];
                float u2 = Up[2 * KTOT + k];
                float u3 = Up[3 * KTOT + k];
                acc[0][0] = fmaf(u0, w.x, acc[0][0]);
                acc[0][1] = fmaf(u0, w.y, acc[0][1]);
                acc[0][2] = fmaf(u0, w.z, acc[0][2]);
                acc[0][3] = fmaf(u0, w.w, acc[0][3]);
                acc[1][0] = fmaf(u1, w.x, acc[1][0]);
                acc[1][1] = fmaf(u1, w.y, acc[1][1]);
                acc[1][2] = fmaf(u1, w.z, acc[1][2]);
                acc[1][3] = fmaf(u1, w.w, acc[1][3]);
                acc[2][0] = fmaf(u2, w.x, acc[2][0]);
                acc[2][1] = fmaf(u2, w.y, acc[2][1]);
                acc[2][2] = fmaf(u2, w.z, acc[2][2]);
                acc[2][3] = fmaf(u2, w.w, acc[2][3]);
                acc[3][0] = fmaf(u3, w.x, acc[3][0]);
                acc[3][1] = fmaf(u3, w.y, acc[3][1]);
                acc[3][2] = fmaf(u3, w.z, acc[3][2]);
                acc[3][3] = fmaf(u3, w.w, acc[3][3]);
            }
            __syncthreads();
        }

        const int cbase = (cc << 6) + (tx << 2);
        if (cbase < GCOLS) {
            #pragma unroll
            for (int i = 0; i < 4; i++) {
                float4 v = make_float4(acc[i][0], acc[i][1], acc[i][2], acc[i][3]);
                *(float4*)&g_scr[(size_t)(row0 + (ty << 2) + i) * GCOLS + cbase] = v;
            }
        }
    }
}

// ---------------- K2: GRU elementwise + MLP GEMM + BN partial sums ----------------
#define SMEM2_FLOATS (6500 + 6500 + 1024)

__global__ void __launch_bounds__(256, 1)
k2_gru(const int* __restrict__ n_id, const float* __restrict__ memory,
       const float* __restrict__ W1, const float* __restrict__ b1) {
    extern __shared__ float sh[];
    float* hn  = sh;            // [100][65] k-major h_new
    float* W1s = sh + 6500;     // [100][65] k-major W1
    float* red = sh + 13000;    // [16][64]
    __shared__ int s_nid[64];

    const int tid  = threadIdx.x;
    const int row0 = blockIdx.x << 6;

    if (tid < 64) s_nid[tid] = n_id[row0 + tid];
    for (int i = tid; i < 6400; i += 256) {
        int ch = i / 100, k = i - ch * 100;
        W1s[k * 65 + ch] = W1[i];
    }
    __syncthreads();

    for (int i = tid; i < 6400; i += 256) {
        int r = i / 100, j = i - r * 100;
        const float* g = &g_scr[(size_t)(row0 + r) * GCOLS];
        float h  = memory[(size_t)s_nid[r] * DMEM + j];
        float xr = g[j]       + B400[j];
        float xz = g[100 + j] + B400[100 + j];
        float xn = g[200 + j] + B400[200 + j];
        float xh = g[300 + j] + B400[300 + j];
        float rr = 1.f / (1.f + expf(-xr));
        float zz = 1.f / (1.f + expf(-xz));
        float nn = tanhf(fmaf(rr, xh, xn));
        hn[j * 65 + r] = (1.f - zz) * nn + zz * h;
    }
    __syncthreads();

    const int tx = tid & 15, ty = tid >> 4;
    float acc[4][4];
    #pragma unroll
    for (int i = 0; i < 4; i++)
        #pragma unroll
        for (int j = 0; j < 4; j++) acc[i][j] = 0.f;

    const float* hp = &hn[ty << 2];
    const float* wp = &W1s[tx << 2];
    #pragma unroll 4
    for (int k = 0; k < 100; k++) {
        float u0 = hp[k * 65 + 0], u1 = hp[k * 65 + 1], u2 = hp[k * 65 + 2], u3 = hp[k * 65 + 3];
        float w0 = wp[k * 65 + 0], w1 = wp[k * 65 + 1], w2 = wp[k * 65 + 2], w3 = wp[k * 65 + 3];
        acc[0][0] = fmaf(u0, w0, acc[0][0]); acc[0][1] = fmaf(u0, w1, acc[0][1]);
        acc[0][2] = fmaf(u0, w2, acc[0][2]); acc[0][3] = fmaf(u0, w3, acc[0][3]);
        acc[1][0] = fmaf(u1, w0, acc[1][0]); acc[1][1] = fmaf(u1, w1, acc[1][1]);
        acc[1][2] = fmaf(u1, w2, acc[1][2]); acc[1][3] = fmaf(u1, w3, acc[1][3]);
        acc[2][0] = fmaf(u2, w0, acc[2][0]); acc[2][1] = fmaf(u2, w1, acc[2][1]);
        acc[2][2] = fmaf(u2, w2, acc[2][2]); acc[2][3] = fmaf(u2, w3, acc[2][3]);
        acc[3][0] = fmaf(u3, w0, acc[3][0]); acc[3][1] = fmaf(u3, w1, acc[3][1]);
        acc[3][2] = fmaf(u3, w2, acc[3][2]); acc[3][3] = fmaf(u3, w3, acc[3][3]);
    }

    float bb0 = b1[(tx << 2) + 0], bb1 = b1[(tx << 2) + 1];
    float bb2 = b1[(tx << 2) + 2], bb3 = b1[(tx << 2) + 3];
    float ls[4] = {0.f, 0.f, 0.f, 0.f}, lq[4] = {0.f, 0.f, 0.f, 0.f};
    #pragma unroll
    for (int i = 0; i < 4; i++) {
        float v0 = fmaxf(acc[i][0] + bb0, 0.f);
        float v1 = fmaxf(acc[i][1] + bb1, 0.f);
        float v2 = fmaxf(acc[i][2] + bb2, 0.f);
        float v3 = fmaxf(acc[i][3] + bb3, 0.f);
        *(float4*)&a_scr[(size_t)(row0 + (ty << 2) + i) * 64 + (tx << 2)] =
            make_float4(v0, v1, v2, v3);
        ls[0] += v0; ls[1] += v1; ls[2] += v2; ls[3] += v3;
        lq[0] += v0 * v0; lq[1] += v1 * v1; lq[2] += v2 * v2; lq[3] += v3 * v3;
    }

    #pragma unroll
    for (int j = 0; j < 4; j++) red[ty * 64 + (tx << 2) + j] = ls[j];
    __syncthreads();
    if (tid < 64) {
        float s = 0.f;
        #pragma unroll
        for (int t = 0; t < 16; t++) s += red[t * 64 + tid];
        p_sum[(size_t)blockIdx.x * 64 + tid] = s;
    }
    __syncthreads();
    #pragma unroll
    for (int j = 0; j < 4; j++) red[ty * 64 + (tx << 2) + j] = lq[j];
    __syncthreads();
    if (tid < 64) {
        float s = 0.f;
        #pragma unroll
        for (int t = 0; t < 16; t++) s += red[t * 64 + tid];
        p_sq[(size_t)blockIdx.x * 64 + tid] = s;
    }
}

// ---------------- K3a: finalize BN stats, fold into W2/b2 ----------------
__global__ void k3_stats(const float* __restrict__ W2, const float* __restrict__ b2,
                         const float* __restrict__ gamma, const float* __restrict__ beta) {
    __shared__ float ssum[256], ssq[256];
    __shared__ float sscale[64], sshift[64];
    int tid = threadIdx.x;
    int ch = tid & 63, part = tid >> 6;
    float s = 0.f, q = 0.f;
    for (int b = part * 1024; b < (part + 1) * 1024; b++) {
        s += p_sum[b * 64 + ch];
        q += p_sq[b * 64 + ch];
    }
    ssum[tid] = s; ssq[tid] = q;
    __syncthreads();
    if (tid < 64) {
        float S = ssum[tid] + ssum[tid + 64] + ssum[tid + 128] + ssum[tid + 192];
        float Q = ssq[tid] + ssq[tid + 64] + ssq[tid + 128] + ssq[tid + 192];
        const float invN = 1.f / 262144.f;
        float mu  = S * invN;
        float var = fmaxf(Q * invN - mu * mu, 0.f);
        float sc  = rsqrtf(var + 1e-5f) * gamma[tid];
        sscale[tid] = sc;
        sshift[tid] = beta[tid] - mu * sc;
    }
    __syncthreads();
    if (tid < 128) W2e[tid] = W2[tid] * sscale[tid & 63];
    if (tid < 2) {
        float acc = b2[tid];
        for (int j = 0; j < 64; j++) acc += sshift[j] * W2[tid * 64 + j];
        b2e[tid] = acc;
    }
}

// ---------------- K3b: out = a @ W2e^T + b2e ----------------
__global__ void __launch_bounds__(256) k3_out(float* __restrict__ out) {
    __shared__ float w2s[128];
    __shared__ float b2s[2];
    int tid = threadIdx.x;
    if (tid < 128) w2s[tid] = W2e[tid];
    if (tid < 2)   b2s[tid] = b2e[tid];
    __syncthreads();
    size_t row = (size_t)blockIdx.x * 256 + tid;
    const float4* ap = (const float4*)&a_scr[row * 64];
    float o0 = b2s[0], o1 = b2s[1];
    #pragma unroll
    for (int q4 = 0; q4 < 16; q4++) {
        float4 v = ap[q4];
        int j = q4 * 4;
        o0 += v.x * w2s[j] + v.y * w2s[j + 1] + v.z * w2s[j + 2] + v.w * w2s[j + 3];
        o1 += v.x * w2s[64 + j] + v.y * w2s[64 + j + 1] + v.z * w2s[64 + j + 2] + v.w * w2s[64 + j + 3];
    }
    out[row * 2]     = o0;
    out[row * 2 + 1] = o1;
}

// ---------------- launch ----------------
extern "C" void kernel_launch(void* const* d_in, const int* in_sizes, int n_in,
                              void* d_out, int out_size) {
    const int*   n_id        = (const int*)d_in[0];
    const float* memory      = (const float*)d_in[1];
    const int*   last_update = (const int*)d_in[2];
    const int*   store_src   = (const int*)d_in[3];
    const int*   store_dst   = (const int*)d_in[4];
    const int*   store_t     = (const int*)d_in[5];
    const float* store_msg   = (const float*)d_in[6];
    const float* time_w      = (const float*)d_in[7];
    const float* time_b      = (const float*)d_in[8];
    const float* W_ih        = (const float*)d_in[9];
    const float* b_ih        = (const float*)d_in[10];
    const float* W_hh        = (const float*)d_in[11];
    const float* b_hh        = (const float*)d_in[12];
    const float* W1          = (const float*)d_in[13];
    const float* b1          = (const float*)d_in[14];
    const float* gamma       = (const float*)d_in[15];
    const float* beta        = (const float*)d_in[16];
    const float* W2          = (const float*)d_in[17];
    const float* b2          = (const float*)d_in[18];
    float* out = (float*)d_out;

    const int smem1 = SMEM1_FLOATS * 4;   // ~120.6 KB
    const int smem2 = SMEM2_FLOATS * 4;   // ~56.1 KB
    cudaFuncSetAttribute(k1_gemm, cudaFuncAttributeMaxDynamicSharedMemorySize, smem1);
    cudaFuncSetAttribute(k2_gru,  cudaFuncAttributeMaxDynamicSharedMemorySize, smem2);

    k0_prep<<<256, 256>>>(W_ih, W_hh, b_ih, b_hh);
    k1_gemm<<<NBLK, 256, smem1>>>(n_id, memory, last_update, store_src, store_dst,
                                  store_t, store_msg, time_w, time_b);
    k2_gru<<<NBLK, 256, smem2>>>(n_id, memory, W1, b1);
    k3_stats<<<1, 256>>>(W2, b2, gamma, beta);
    k3_out<<<1024, 256>>>(out);
}

// round 3
// speedup vs baseline: 1.1268x; 1.1268x over previous
#include <cuda_runtime.h>
#include <math.h>

// ---------------- problem constants ----------------
#define BATCH   262144
#define DMEM    100
#define NBLK    4096          // BATCH / 64
#define GCOLS   400           // [g_r(100), g_z(100), i_n(100), h_n(100)]
#define KTOT    404           // [mem[src](100), mem[dst](100), msg(4), t_enc(100), h(100)]
#define WB_COLS 448           // GCOLS padded to 7*64

typedef unsigned long long u64;

// ---------------- scratch (static device globals; no allocation) ----------------
__device__ float g_scr[104857600];   // BATCH x 400
__device__ float a_scr[16777216];    // BATCH x 64
__device__ float Wbig[404 * 448];    // k-major packed weights, zero padded
__device__ float B400[400];          // fused biases
__device__ float p_sum[NBLK * 64];
__device__ float p_sq[NBLK * 64];
__device__ float Ssum[64];
__device__ float Ssq[64];
__device__ float W2e[128];
__device__ float b2e[2];

// ---------------- f32x2 packed-FMA helpers (sm_103a) ----------------
__device__ __forceinline__ void fma2(u64 &d, u64 a, u64 b) {
    asm("fma.rn.f32x2 %0, %1, %2, %0;" : "+l"(d) : "l"(a), "l"(b));
}
__device__ __forceinline__ u64 pk2(float lo, float hi) {
    u64 r; asm("mov.b64 %0, {%1, %2};" : "=l"(r) : "f"(lo), "f"(hi)); return r;
}
__device__ __forceinline__ float2 upk2(u64 v) {
    float2 f; asm("mov.b64 {%0, %1}, %2;" : "=f"(f.x), "=f"(f.y) : "l"(v)); return f;
}

// accurate cos via fp32 Cody-Waite 3-term (|x| < ~2e5 -> k < 2^15, k*C1/k*C2 exact)
__device__ __forceinline__ float cos_acc(float x) {
    const float INV2PI = 0.15915494309189534f;
    const float C1 = 6.28125f;                 // 8-bit mantissa chunk of 2*pi
    const float C2 = 1.934051513671875e-3f;    // 9-bit chunk (507 * 2^-18)
    const float C3 = 1.2556659146021878e-6f;   // remainder
    float k = rintf(x * INV2PI);
    float r = fmaf(k, -C1, x);
    r = fmaf(k, -C2, r);
    r = fmaf(k, -C3, r);
    return cosf(r);
}

// ---------------- K0: pack weights + biases ----------------
__global__ void k0_prep(const float* __restrict__ W_ih, const float* __restrict__ W_hh,
                        const float* __restrict__ b_ih, const float* __restrict__ b_hh) {
    int idx0 = blockIdx.x * blockDim.x + threadIdx.x;
    int stride = gridDim.x * blockDim.x;
    for (int idx = idx0; idx < KTOT * WB_COLS; idx += stride) {
        int k = idx / WB_COLS;
        int c = idx - k * WB_COLS;
        float v = 0.f;
        if (c < GCOLS) {
            if (k < 304) {                   // x part
                if (c < 300) v = W_ih[c * 304 + k];
            } else {                          // h part
                int kh = k - 304;
                if (c < 200)       v = W_hh[c * 100 + kh];
                else if (c >= 300) v = W_hh[(c - 100) * 100 + kh];
            }
        }
        Wbig[idx] = v;
    }
    if (idx0 < 400) {
        int c = idx0;
        float bv;
        if (c < 200)      bv = b_ih[c] + b_hh[c];
        else if (c < 300) bv = b_ih[c];
        else              bv = b_hh[c - 100];
        B400[c] = bv;
    }
}

// ---------------- K1: gather + t_enc + big GEMM (G = U @ Wbig) ----------------
// block = 256 threads, 64 rows/block. Shared: U [64][404] row-major,
// Wsh double-buffered [2][64][64], time params. 4x4 microtile, FFMA2 pairs.
#define SMEM1_FLOATS (64 * 404 + 2 * 64 * 64 + 200)

__global__ void __launch_bounds__(256, 1)
k1_gemm(const int* __restrict__ n_id, const float* __restrict__ memory,
        const int* __restrict__ last_update, const int* __restrict__ store_src,
        const int* __restrict__ store_dst, const int* __restrict__ store_t,
        const float* __restrict__ store_msg, const float* __restrict__ time_w,
        const float* __restrict__ time_b) {
    extern __shared__ float sh[];
    float* Ush = sh;                    // [64][404]
    float* Wsh = sh + 64 * 404;         // [2][64][64]
    float* stw = Wsh + 2 * 64 * 64;     // [100]
    float* stb = stw + 100;             // [100]
    __shared__ int   s_src[64], s_dst[64], s_nid[64];
    __shared__ float s_dt[64];

    const int tid  = threadIdx.x;
    const int row0 = blockIdx.x << 6;

    if (tid < 64) {
        int nid = n_id[row0 + tid];
        s_nid[tid] = nid;
        s_src[tid] = store_src[nid];
        s_dst[tid] = store_dst[nid];
        s_dt[tid]  = (float)(store_t[nid] - last_update[nid]);
    }
    if (tid < 100) { stw[tid] = time_w[tid]; stb[tid] = time_b[tid]; }
    __syncthreads();

    // build U tile: gathers + msg + time encoding (coalesced per row)
    for (int i = tid; i < 6400; i += 256) {
        int r = i / 100;
        int c = i - r * 100;
        Ush[r * KTOT + c]        = memory[(size_t)s_src[r] * DMEM + c];
        Ush[r * KTOT + 100 + c]  = memory[(size_t)s_dst[r] * DMEM + c];
        Ush[r * KTOT + 304 + c]  = memory[(size_t)s_nid[r] * DMEM + c];
        float arg = __fadd_rn(__fmul_rn(s_dt[r], stw[c]), stb[c]);
        Ush[r * KTOT + 204 + c]  = cos_acc(arg);
    }
    { // msg (4 per row)
        int r = tid >> 2, m = tid & 3;
        Ush[r * KTOT + 200 + m] = store_msg[(size_t)s_nid[r] * 4 + m];
    }

    const int tx = tid & 15;   // col group (4 cols)
    const int ty = tid >> 4;   // row group (4 rows)

    // prefetch first W block (cc=0, kk=0) into buffer 0
    {
        float4 wr[4];
        #pragma unroll
        for (int t = 0; t < 4; t++) {
            int i = tid + (t << 8);
            int k = i >> 4, c4 = (i & 15) << 2;
            wr[t] = *(const float4*)&Wbig[k * WB_COLS + c4];
        }
        #pragma unroll
        for (int t = 0; t < 4; t++)
            ((float4*)Wsh)[tid + (t << 8)] = wr[t];
    }
    __syncthreads();

    u64 acc[4][2];
    #pragma unroll
    for (int i = 0; i < 4; i++) { acc[i][0] = 0ULL; acc[i][1] = 0ULL; }

    int cc = 0, kk = 0, buf = 0;
    while (true) {
        // next (cc,kk)
        int ncc = cc, nkk = kk + 64;
        if (nkk >= KTOT) { ncc = cc + 1; nkk = (ncc >= 5) ? 304 : 0; }
        const bool has_next = (ncc < 7);

        // issue LDG for next W tile
        float4 wr[4];
        if (has_next) {
            #pragma unroll
            for (int t = 0; t < 4; t++) {
                int i = tid + (t << 8);
                int k = i >> 4, c4 = (i & 15) << 2;
                int kg = nkk + k;
                wr[t] = (kg < KTOT) ? *(const float4*)&Wbig[kg * WB_COLS + (ncc << 6) + c4]
                                    : make_float4(0.f, 0.f, 0.f, 0.f);
            }
        }

        // compute current k-block
        {
            const float* Up = &Ush[(ty << 2) * KTOT + kk];
            const float* Wp = Wsh + buf * 4096 + (tx << 2);
            #pragma unroll 8
            for (int k = 0; k < 64; k++) {
                float4 w = *(const float4*)(Wp + (k << 6));
                u64 wlo = pk2(w.x, w.y);
                u64 whi = pk2(w.z, w.w);
                float u0 = Up[k];
                float u1 = Up[KTOT + k];
                float u2 = Up[2 * KTOT + k];
                float u3 = Up[3 * KTOT + k];
                u64 p;
                p = pk2(u0, u0); fma2(acc[0][0], p, wlo); fma2(acc[0][1], p, whi);
                p = pk2(u1, u1); fma2(acc[1][0], p, wlo); fma2(acc[1][1], p, whi);
                p = pk2(u2, u2); fma2(acc[2][0], p, wlo); fma2(acc[2][1], p, whi);
                p = pk2(u3, u3); fma2(acc[3][0], p, wlo); fma2(acc[3][1], p, whi);
            }
        }

        // cc finished? store + reset
        if (kk + 64 >= KTOT) {
            const int cbase = (cc << 6) + (tx << 2);
            if (cbase < GCOLS) {
                #pragma unroll
                for (int i = 0; i < 4; i++) {
                    float2 lo = upk2(acc[i][0]);
                    float2 hi = upk2(acc[i][1]);
                    *(float4*)&g_scr[(size_t)(row0 + (ty << 2) + i) * GCOLS + cbase] =
                        make_float4(lo.x, lo.y, hi.x, hi.y);
                }
            }
            #pragma unroll
            for (int i = 0; i < 4; i++) { acc[i][0] = 0ULL; acc[i][1] = 0ULL; }
        }

        if (!has_next) break;

        // stage next tile into the other buffer; single sync
        #pragma unroll
        for (int t = 0; t < 4; t++)
            ((float4*)(Wsh + (buf ^ 1) * 4096))[tid + (t << 8)] = wr[t];
        __syncthreads();
        buf ^= 1; cc = ncc; kk = nkk;
    }
}

// ---------------- K2: GRU elementwise + MLP GEMM + BN partial sums ----------------
#define K2S 68   // padded row stride (floats) for hn / W1s, keeps float4 alignment
#define SMEM2_FLOATS (100 * K2S + 100 * K2S + 1024)

__global__ void __launch_bounds__(256, 1)
k2_gru(const int* __restrict__ n_id, const float* __restrict__ memory,
       const float* __restrict__ W1, const float* __restrict__ b1) {
    extern __shared__ float sh[];
    float* hn  = sh;                 // [100][68] k-major h_new (64 used)
    float* W1s = sh + 100 * K2S;     // [100][68] k-major W1 (64 used)
    float* red = sh + 200 * K2S;     // [16][64]
    __shared__ int s_nid[64];

    const int tid  = threadIdx.x;
    const int row0 = blockIdx.x << 6;

    if (tid < 64) s_nid[tid] = n_id[row0 + tid];
    for (int i = tid; i < 6400; i += 256) {
        int ch = i / 100, k = i - ch * 100;
        W1s[k * K2S + ch] = W1[i];
    }
    __syncthreads();

    for (int i = tid; i < 6400; i += 256) {
        int r = i / 100, j = i - r * 100;
        const float* g = &g_scr[(size_t)(row0 + r) * GCOLS];
        float h  = memory[(size_t)s_nid[r] * DMEM + j];
        float xr = g[j]       + B400[j];
        float xz = g[100 + j] + B400[100 + j];
        float xn = g[200 + j] + B400[200 + j];
        float xh = g[300 + j] + B400[300 + j];
        float rr = 1.f / (1.f + expf(-xr));
        float zz = 1.f / (1.f + expf(-xz));
        float nn = tanhf(fmaf(rr, xh, xn));
        hn[j * K2S + r] = (1.f - zz) * nn + zz * h;
    }
    __syncthreads();

    const int tx = tid & 15, ty = tid >> 4;
    u64 acc[4][2];
    #pragma unroll
    for (int i = 0; i < 4; i++) { acc[i][0] = 0ULL; acc[i][1] = 0ULL; }

    const float* hp = &hn[ty << 2];
    const float* wp = &W1s[tx << 2];
    #pragma unroll 4
    for (int k = 0; k < 100; k++) {
        float4 u = *(const float4*)(hp + k * K2S);
        float4 w = *(const float4*)(wp + k * K2S);
        u64 wlo = pk2(w.x, w.y);
        u64 whi = pk2(w.z, w.w);
        u64 p;
        p = pk2(u.x, u.x); fma2(acc[0][0], p, wlo); fma2(acc[0][1], p, whi);
        p = pk2(u.y, u.y); fma2(acc[1][0], p, wlo); fma2(acc[1][1], p, whi);
        p = pk2(u.z, u.z); fma2(acc[2][0], p, wlo); fma2(acc[2][1], p, whi);
        p = pk2(u.w, u.w); fma2(acc[3][0], p, wlo); fma2(acc[3][1], p, whi);
    }

    float bb0 = b1[(tx << 2) + 0], bb1 = b1[(tx << 2) + 1];
    float bb2 = b1[(tx << 2) + 2], bb3 = b1[(tx << 2) + 3];
    float ls[4] = {0.f, 0.f, 0.f, 0.f}, lq[4] = {0.f, 0.f, 0.f, 0.f};
    #pragma unroll
    for (int i = 0; i < 4; i++) {
        float2 lo = upk2(acc[i][0]);
        float2 hi = upk2(acc[i][1]);
        float v0 = fmaxf(lo.x + bb0, 0.f);
        float v1 = fmaxf(lo.y + bb1, 0.f);
        float v2 = fmaxf(hi.x + bb2, 0.f);
        float v3 = fmaxf(hi.y + bb3, 0.f);
        *(float4*)&a_scr[(size_t)(row0 + (ty << 2) + i) * 64 + (tx << 2)] =
            make_float4(v0, v1, v2, v3);
        ls[0] += v0; ls[1] += v1; ls[2] += v2; ls[3] += v3;
        lq[0] += v0 * v0; lq[1] += v1 * v1; lq[2] += v2 * v2; lq[3] += v3 * v3;
    }

    #pragma unroll
    for (int j = 0; j < 4; j++) red[ty * 64 + (tx << 2) + j] = ls[j];
    __syncthreads();
    if (tid < 64) {
        float s = 0.f;
        #pragma unroll
        for (int t = 0; t < 16; t++) s += red[t * 64 + tid];
        p_sum[(size_t)blockIdx.x * 64 + tid] = s;
    }
    __syncthreads();
    #pragma unroll
    for (int j = 0; j < 4; j++) red[ty * 64 + (tx << 2) + j] = lq[j];
    __syncthreads();
    if (tid < 64) {
        float s = 0.f;
        #pragma unroll
        for (int t = 0; t < 16; t++) s += red[t * 64 + tid];
        p_sq[(size_t)blockIdx.x * 64 + tid] = s;
    }
}

// ---------------- K3a: parallel BN reduction (64 blocks, one per channel) ----------------
__global__ void __launch_bounds__(256) k3_red() {
    __shared__ float rs[256], rq[256];
    const int tid = threadIdx.x, ch = blockIdx.x;
    float s = 0.f, q = 0.f;
    for (int b = tid; b < NBLK; b += 256) {
        s += p_sum[b * 64 + ch];
        q += p_sq[b * 64 + ch];
    }
    rs[tid] = s; rq[tid] = q;
    __syncthreads();
    for (int off = 128; off; off >>= 1) {
        if (tid < off) { rs[tid] += rs[tid + off]; rq[tid] += rq[tid + off]; }
        __syncthreads();
    }
    if (tid == 0) { Ssum[ch] = rs[0]; Ssq[ch] = rq[0]; }
}

// ---------------- K3b: finalize BN stats, fold into W2/b2 ----------------
__global__ void k3_stats2(const float* __restrict__ W2, const float* __restrict__ b2,
                          const float* __restrict__ gamma, const float* __restrict__ beta) {
    __shared__ float sscale[64], sshift[64];
    int tid = threadIdx.x;
    if (tid < 64) {
        const float invN = 1.f / 262144.f;
        float mu  = Ssum[tid] * invN;
        float var = fmaxf(Ssq[tid] * invN - mu * mu, 0.f);
        float sc  = rsqrtf(var + 1e-5f) * gamma[tid];
        sscale[tid] = sc;
        sshift[tid] = beta[tid] - mu * sc;
    }
    __syncthreads();
    if (tid < 128) W2e[tid] = W2[tid] * sscale[tid & 63];
    if (tid < 2) {
        float acc = b2[tid];
        for (int j = 0; j < 64; j++) acc += sshift[j] * W2[tid * 64 + j];
        b2e[tid] = acc;
    }
}

// ---------------- K3c: out = a @ W2e^T + b2e ----------------
__global__ void __launch_bounds__(256) k3_out(float* __restrict__ out) {
    __shared__ float w2s[128];
    __shared__ float b2s[2];
    int tid = threadIdx.x;
    if (tid < 128) w2s[tid] = W2e[tid];
    if (tid < 2)   b2s[tid] = b2e[tid];
    __syncthreads();
    size_t row = (size_t)blockIdx.x * 256 + tid;
    const float4* ap = (const float4*)&a_scr[row * 64];
    float o0 = b2s[0], o1 = b2s[1];
    #pragma unroll
    for (int q4 = 0; q4 < 16; q4++) {
        float4 v = ap[q4];
        int j = q4 * 4;
        o0 += v.x * w2s[j] + v.y * w2s[j + 1] + v.z * w2s[j + 2] + v.w * w2s[j + 3];
        o1 += v.x * w2s[64 + j] + v.y * w2s[64 + j + 1] + v.z * w2s[64 + j + 2] + v.w * w2s[64 + j + 3];
    }
    out[row * 2]     = o0;
    out[row * 2 + 1] = o1;
}

// ---------------- launch ----------------
extern "C" void kernel_launch(void* const* d_in, const int* in_sizes, int n_in,
                              void* d_out, int out_size) {
    const int*   n_id        = (const int*)d_in[0];
    const float* memory      = (const float*)d_in[1];
    const int*   last_update = (const int*)d_in[2];
    const int*   store_src   = (const int*)d_in[3];
    const int*   store_dst   = (const int*)d_in[4];
    const int*   store_t     = (const int*)d_in[5];
    const float* store_msg   = (const float*)d_in[6];
    const float* time_w      = (const float*)d_in[7];
    const float* time_b      = (const float*)d_in[8];
    const float* W_ih        = (const float*)d_in[9];
    const float* b_ih        = (const float*)d_in[10];
    const float* W_hh        = (const float*)d_in[11];
    const float* b_hh        = (const float*)d_in[12];
    const float* W1          = (const float*)d_in[13];
    const float* b1          = (const float*)d_in[14];
    const float* gamma       = (const float*)d_in[15];
    const float* beta        = (const float*)d_in[16];
    const float* W2          = (const float*)d_in[17];
    const float* b2          = (const float*)d_in[18];
    float* out = (float*)d_out;

    const int smem1 = SMEM1_FLOATS * 4;   // ~134 KB
    const int smem2 = SMEM2_FLOATS * 4;   // ~58.5 KB
    cudaFuncSetAttribute(k1_gemm, cudaFuncAttributeMaxDynamicSharedMemorySize, smem1);
    cudaFuncSetAttribute(k2_gru,  cudaFuncAttributeMaxDynamicSharedMemorySize, smem2);

    k0_prep<<<256, 256>>>(W_ih, W_hh, b_ih, b_hh);
    k1_gemm<<<NBLK, 256, smem1>>>(n_id, memory, last_update, store_src, store_dst,
                                  store_t, store_msg, time_w, time_b);
    k2_gru<<<NBLK, 256, smem2>>>(n_id, memory, W1, b1);
    k3_red<<<64, 256>>>();
    k3_stats2<<<1, 128>>>(W2, b2, gamma, beta);
    k3_out<<<1024, 256>>>(out);
}